// round 1
// baseline (speedup 1.0000x reference)
#include <cuda_runtime.h>
#include <math.h>
#include <stdint.h>

// Problem constants
#define M_TOT 8192          // B*L
#define KD    1024          // D_IN == D_OUT
#define ND    1024
#define EPSF  1.1920929e-07f
#define LAM_INIT 0.2f
#define ONE_MINUS_LAM_INIT 0.8f
#define SCALE_ATT 0.044194173824159216f   // 1/sqrt(512)

// -------- scratch (no allocations allowed; __device__ globals) --------
__device__ float g_xn[(size_t)M_TOT * KD];
__device__ float g_Q [(size_t)M_TOT * ND];
__device__ float g_K [(size_t)M_TOT * ND];
__device__ float g_V [(size_t)M_TOT * ND];
__device__ float g_y [(size_t)M_TOT * ND];
__device__ float g_h [(size_t)M_TOT * ND];

// ============================================================
// rmsnorm over 1024 elems per row. residual!=0 -> out = xn*w + x
// ============================================================
__global__ void rmsnorm_k(const float* __restrict__ x, const float* __restrict__ w,
                          float* __restrict__ y, int residual)
{
    int row = blockIdx.x;
    int tid = threadIdx.x;                       // 256 threads, 4 floats each
    const float4* xr = (const float4*)(x + (size_t)row * 1024);
    float4 v = xr[tid];
    float ss = v.x*v.x + v.y*v.y + v.z*v.z + v.w*v.w;
    #pragma unroll
    for (int o = 16; o > 0; o >>= 1) ss += __shfl_xor_sync(0xffffffffu, ss, o);
    __shared__ float sp[8];
    __shared__ float sscale;
    if ((tid & 31) == 0) sp[tid >> 5] = ss;
    __syncthreads();
    if (tid == 0) {
        float s = 0.f;
        #pragma unroll
        for (int i = 0; i < 8; i++) s += sp[i];
        sscale = rsqrtf(s * (1.0f/1024.0f) + EPSF);
    }
    __syncthreads();
    float sc = sscale;
    float4 wv = ((const float4*)w)[tid];
    float4 o;
    o.x = v.x * sc * wv.x; o.y = v.y * sc * wv.y;
    o.z = v.z * sc * wv.z; o.w = v.w * sc * wv.w;
    if (residual) { o.x += v.x; o.y += v.y; o.z += v.z; o.w += v.w; }
    ((float4*)(y + (size_t)row * 1024))[tid] = o;
}

// ============================================================
// per-position differential linear attention (one block per (b,l))
// ============================================================
__global__ void attn_k(const float* __restrict__ Q, const float* __restrict__ K,
                       const float* __restrict__ V, const float* __restrict__ lp,
                       const float* __restrict__ g2, float* __restrict__ out)
{
    __shared__ float sQ[1024], sK[1024], sV[1024];
    __shared__ float skv[64 * 64];
    __shared__ float sA[1024];
    __shared__ float sS[16];
    int pos = blockIdx.x, tid = threadIdx.x;     // 256 threads
    size_t base = (size_t)pos * 1024;

    for (int i = tid; i < 1024; i += 256) {
        float q = Q[base + i], k = K[base + i];
        sQ[i] = (q > 0.f) ? q : expm1f(q);       // elu
        sK[i] = (k > 0.f) ? k : expm1f(k);
        sV[i] = V[base + i];
    }
    __syncthreads();

    // kv[d][e] = SCALE * sum_h phi(K)[h,d] * V[h,e]   (d,e in 0..63)
    for (int idx = tid; idx < 4096; idx += 256) {
        int d = idx >> 6, e = idx & 63;
        float s = 0.f;
        #pragma unroll
        for (int h = 0; h < 16; h++) s += sK[h * 64 + d] * sV[h * 64 + e];
        skv[idx] = s * SCALE_ATT;
    }
    __syncthreads();

    float lam = expf(lp[0] * lp[1]) - expf(lp[2] * lp[3]) + LAM_INIT;

    // attn[h][e] = a1 - lam*a2
    for (int idx = tid; idx < 1024; idx += 256) {
        int h = idx >> 6, e = idx & 63;
        float s1 = 0.f, s2 = 0.f;
        #pragma unroll
        for (int d = 0; d < 32; d++) {
            s1 += sQ[h * 64 + d]      * skv[d * 64 + e];
            s2 += sQ[h * 64 + 32 + d] * skv[(32 + d) * 64 + e];
        }
        sA[idx] = s1 - lam * s2;
    }
    __syncthreads();

    if (tid < 16) {
        float ss = 0.f;
        #pragma unroll
        for (int e = 0; e < 64; e++) { float v = sA[tid * 64 + e]; ss += v * v; }
        sS[tid] = rsqrtf(ss * (1.0f/64.0f) + EPSF) * ONE_MINUS_LAM_INIT;
    }
    __syncthreads();

    for (int idx = tid; idx < 1024; idx += 256) {
        int h = idx >> 6, e = idx & 63;
        out[base + idx] = sA[idx] * sS[h] * g2[e];
    }
}

// ============================================================
// C[M,N] = A[M,K] @ B[N,K]^T + bias, fused epilogue.
// EPI: 0 = bias, 1 = bias+exact GELU, 2 = bias+residual
// 128x128 block tile, KT=8, 8x8 per thread, 256 threads,
// register-double-buffered global loads.
// ============================================================
__device__ __forceinline__ float gelu_exact(float v) {
    return 0.5f * v * (1.0f + erff(v * 0.70710678118654752f));
}

template<int EPI>
__global__ void __launch_bounds__(256, 2)
gemm128(const float* __restrict__ A, const float* __restrict__ B,
        const float* __restrict__ bias, const float* __restrict__ R,
        float* __restrict__ C, int M, int N, int K)
{
    __shared__ float As[8][132];
    __shared__ float Bs[8][132];
    int tid = threadIdx.x;
    int tx = tid & 15, ty = tid >> 4;
    int bm = blockIdx.y * 128, bn = blockIdx.x * 128;

    int lrow = tid >> 1;            // 0..127
    int lk   = (tid & 1) * 4;       // 0 or 4
    const float* Ag = A + (size_t)(bm + lrow) * K + lk;
    const float* Bg = B + (size_t)(bn + lrow) * K + lk;

    float acc[8][8];
    #pragma unroll
    for (int i = 0; i < 8; i++)
        #pragma unroll
        for (int j = 0; j < 8; j++) acc[i][j] = 0.f;

    float4 av = *(const float4*)(Ag);
    float4 bv = *(const float4*)(Bg);

    for (int k0 = 0; k0 < K; k0 += 8) {
        __syncthreads();
        As[lk+0][lrow] = av.x; As[lk+1][lrow] = av.y;
        As[lk+2][lrow] = av.z; As[lk+3][lrow] = av.w;
        Bs[lk+0][lrow] = bv.x; Bs[lk+1][lrow] = bv.y;
        Bs[lk+2][lrow] = bv.z; Bs[lk+3][lrow] = bv.w;
        __syncthreads();
        if (k0 + 8 < K) {
            av = *(const float4*)(Ag + k0 + 8);
            bv = *(const float4*)(Bg + k0 + 8);
        }
        #pragma unroll
        for (int kk = 0; kk < 8; kk++) {
            float a[8], b[8];
            *(float4*)&a[0] = *(const float4*)&As[kk][ty * 4];
            *(float4*)&a[4] = *(const float4*)&As[kk][64 + ty * 4];
            *(float4*)&b[0] = *(const float4*)&Bs[kk][tx * 4];
            *(float4*)&b[4] = *(const float4*)&Bs[kk][64 + tx * 4];
            #pragma unroll
            for (int i = 0; i < 8; i++)
                #pragma unroll
                for (int j = 0; j < 8; j++)
                    acc[i][j] += a[i] * b[j];
        }
    }

    #pragma unroll
    for (int i = 0; i < 8; i++) {
        int r = bm + ((i < 4) ? (ty * 4 + i) : (64 + ty * 4 + (i - 4)));
        #pragma unroll
        for (int jg = 0; jg < 2; jg++) {
            int c = bn + jg * 64 + tx * 4;
            float4 o;
            o.x = acc[i][jg*4+0] + bias[c+0];
            o.y = acc[i][jg*4+1] + bias[c+1];
            o.z = acc[i][jg*4+2] + bias[c+2];
            o.w = acc[i][jg*4+3] + bias[c+3];
            if (EPI == 1) {
                o.x = gelu_exact(o.x); o.y = gelu_exact(o.y);
                o.z = gelu_exact(o.z); o.w = gelu_exact(o.w);
            } else if (EPI == 2) {
                const float4 rv = *(const float4*)&R[(size_t)r * N + c];
                o.x += rv.x; o.y += rv.y; o.z += rv.z; o.w += rv.w;
            }
            *(float4*)&C[(size_t)r * N + c] = o;
        }
    }
}

// ============================================================
extern "C" void kernel_launch(void* const* d_in, const int* in_sizes, int n_in,
                              void* d_out, int out_size)
{
    const float* x   = (const float*)d_in[0];
    const float* Wq  = (const float*)d_in[1];
    const float* bq  = (const float*)d_in[2];
    const float* Wk  = (const float*)d_in[3];
    const float* bk  = (const float*)d_in[4];
    const float* Wv  = (const float*)d_in[5];
    const float* bv  = (const float*)d_in[6];
    const float* lp  = (const float*)d_in[7];
    const float* g1  = (const float*)d_in[8];
    const float* g2  = (const float*)d_in[9];
    const float* g3  = (const float*)d_in[10];
    const float* Wf1 = (const float*)d_in[11];
    const float* bf1 = (const float*)d_in[12];
    const float* Wf2 = (const float*)d_in[13];
    const float* bf2 = (const float*)d_in[14];
    float* out = (float*)d_out;

    float *xn, *Qp, *Kp, *Vp, *yp, *hp;
    cudaGetSymbolAddress((void**)&xn, g_xn);
    cudaGetSymbolAddress((void**)&Qp, g_Q);
    cudaGetSymbolAddress((void**)&Kp, g_K);
    cudaGetSymbolAddress((void**)&Vp, g_V);
    cudaGetSymbolAddress((void**)&yp, g_y);
    cudaGetSymbolAddress((void**)&hp, g_h);

    dim3 gg(ND / 128, M_TOT / 128);   // (8, 64)

    rmsnorm_k<<<M_TOT, 256>>>(x, g1, xn, 0);
    gemm128<0><<<gg, 256>>>(xn, Wq, bq, nullptr, Qp, M_TOT, ND, KD);
    gemm128<0><<<gg, 256>>>(xn, Wk, bk, nullptr, Kp, M_TOT, ND, KD);
    gemm128<0><<<gg, 256>>>(xn, Wv, bv, nullptr, Vp, M_TOT, ND, KD);
    attn_k<<<M_TOT, 256>>>(Qp, Kp, Vp, lp, g2, xn);          // xn reused as raw attn
    rmsnorm_k<<<M_TOT, 256>>>(xn, g3, yp, 1);                // y = rmsnorm(attn)*g3 + attn
    gemm128<1><<<gg, 256>>>(yp, Wf1, bf1, nullptr, hp, M_TOT, ND, KD);
    gemm128<2><<<gg, 256>>>(hp, Wf2, bf2, yp, out, M_TOT, ND, KD);
}

// round 3
// speedup vs baseline: 1.4406x; 1.4406x over previous
#include <cuda_runtime.h>
#include <cuda_bf16.h>
#include <math.h>
#include <stdint.h>

// ---------------- problem constants ----------------
#define M_TOT 8192
#define KD    1024
#define ND    1024
#define KT    3072            // tripled K for bf16 3-product split [hi|lo|hi]x[hi|hi|lo]
#define EPSF  1.1920929e-07f
#define LAM_INIT 0.2f
#define ONE_MINUS_LAM_INIT 0.8f
#define SCALE_ATT 0.044194173824159216f

// ---------------- GEMM tiling ----------------
#define TILE_M 128
#define TILE_N 128
#define KC     32                  // K per stage (bf16)
#define NIT    (KT/KC)             // 96
#define RS     40                  // smem row stride in bf16 (32 + 8 pad) = 80B
#define ST_A   (128*RS*2)          // 10240 B
#define STG    (2*ST_A)            // 20480 B per stage (A+B)
#define STAGES 4
#define SMEM_DYN (STAGES*STG)      // 81920

// ---------------- scratch (__device__ globals; no allocs allowed) ----------------
__device__ float g_xn[(size_t)M_TOT * KD];
__device__ float g_Q [(size_t)M_TOT * ND];
__device__ float g_K [(size_t)M_TOT * ND];
__device__ float g_V [(size_t)M_TOT * ND];
__device__ float g_y [(size_t)M_TOT * ND];
__device__ float g_h [(size_t)M_TOT * ND];
__device__ __align__(128) __nv_bfloat16 g_Ab[(size_t)M_TOT * KT];   // 48MB activations'
__device__ __align__(128) __nv_bfloat16 g_Wb[(size_t)ND * KT];      // 6MB weights'

// ---------------- PTX helpers (base ISA only: sm_80-class) ----------------
__device__ __forceinline__ uint32_t smem_u32(const void* p) {
    uint32_t a;
    asm("{ .reg .u64 t; cvta.to.shared.u64 t, %1; cvt.u32.u64 %0, t; }" : "=r"(a) : "l"(p));
    return a;
}
#define CP_ASYNC16(dst, src) \
    asm volatile("cp.async.cg.shared.global [%0], [%1], 16;" :: "r"(dst), "l"(src) : "memory")
#define CP_COMMIT() asm volatile("cp.async.commit_group;" ::: "memory")
#define CP_WAIT2()  asm volatile("cp.async.wait_group 2;" ::: "memory")

__device__ __forceinline__ void ldm_x4(uint32_t& r0, uint32_t& r1, uint32_t& r2, uint32_t& r3,
                                       uint32_t addr) {
    asm volatile("ldmatrix.sync.aligned.m8n8.x4.shared.b16 {%0,%1,%2,%3}, [%4];"
                 : "=r"(r0), "=r"(r1), "=r"(r2), "=r"(r3) : "r"(addr));
}
__device__ __forceinline__ void mma16816(float& c0, float& c1, float& c2, float& c3,
                                         uint32_t a0, uint32_t a1, uint32_t a2, uint32_t a3,
                                         uint32_t b0, uint32_t b1) {
    asm volatile("mma.sync.aligned.m16n8k16.row.col.f32.bf16.bf16.f32 "
                 "{%0,%1,%2,%3}, {%4,%5,%6,%7}, {%8,%9}, {%0,%1,%2,%3};"
                 : "+f"(c0), "+f"(c1), "+f"(c2), "+f"(c3)
                 : "r"(a0), "r"(a1), "r"(a2), "r"(a3), "r"(b0), "r"(b1));
}

// ---------------- split-convert: fp32 [rows,1024] -> bf16 [rows,3072] = [hi|lo|hi] ----------------
__global__ void cvt3_k(const float* __restrict__ X, __nv_bfloat16* __restrict__ Y)
{
    size_t i4 = (size_t)blockIdx.x * 256 + threadIdx.x;       // float4 index
    float4 v = ((const float4*)X)[i4];
    size_t row = i4 >> 8;
    int    c4  = (int)(i4 & 255);
    float vv[4] = {v.x, v.y, v.z, v.w};
    unsigned short hu[4], lu[4];
    #pragma unroll
    for (int i = 0; i < 4; i++) {
        __nv_bfloat16 h = __float2bfloat16(vv[i]);
        __nv_bfloat16 l = __float2bfloat16(vv[i] - __bfloat162float(h));
        hu[i] = __bfloat16_as_ushort(h);
        lu[i] = __bfloat16_as_ushort(l);
    }
    uint2 hv, lv;
    hv.x = (uint32_t)hu[0] | ((uint32_t)hu[1] << 16);
    hv.y = (uint32_t)hu[2] | ((uint32_t)hu[3] << 16);
    lv.x = (uint32_t)lu[0] | ((uint32_t)lu[1] << 16);
    lv.y = (uint32_t)lu[2] | ((uint32_t)lu[3] << 16);
    __nv_bfloat16* base = Y + row * KT + (size_t)c4 * 4;
    *(uint2*)(base)        = hv;   // section 0: hi  (pairs with W hi)
    *(uint2*)(base + 1024) = lv;   // section 1: lo  (pairs with W hi)
    *(uint2*)(base + 2048) = hv;   // section 2: hi  (pairs with W lo)
}
// weights: [hi|hi|lo]
__global__ void cvt3w_k(const float* __restrict__ X, __nv_bfloat16* __restrict__ Y)
{
    size_t i4 = (size_t)blockIdx.x * 256 + threadIdx.x;
    float4 v = ((const float4*)X)[i4];
    size_t row = i4 >> 8;
    int    c4  = (int)(i4 & 255);
    float vv[4] = {v.x, v.y, v.z, v.w};
    unsigned short hu[4], lu[4];
    #pragma unroll
    for (int i = 0; i < 4; i++) {
        __nv_bfloat16 h = __float2bfloat16(vv[i]);
        __nv_bfloat16 l = __float2bfloat16(vv[i] - __bfloat162float(h));
        hu[i] = __bfloat16_as_ushort(h);
        lu[i] = __bfloat16_as_ushort(l);
    }
    uint2 hv, lv;
    hv.x = (uint32_t)hu[0] | ((uint32_t)hu[1] << 16);
    hv.y = (uint32_t)hu[2] | ((uint32_t)hu[3] << 16);
    lv.x = (uint32_t)lu[0] | ((uint32_t)lu[1] << 16);
    lv.y = (uint32_t)lu[2] | ((uint32_t)lu[3] << 16);
    __nv_bfloat16* base = Y + row * KT + (size_t)c4 * 4;
    *(uint2*)(base)        = hv;
    *(uint2*)(base + 1024) = hv;
    *(uint2*)(base + 2048) = lv;
}

// ---------------- stage loader: cp.async 16B chunks, padded rows ----------------
__device__ __forceinline__ void load_stage(uint32_t sb, const __nv_bfloat16* Ab,
                                           const __nv_bfloat16* Bb, int slot, int kiter, int tid)
{
    const int k0 = kiter * KC;
    const uint32_t stage = sb + slot * STG;
    // A: 512 chunks (128 rows x 4 x 16B), B: 512 chunks; 4 per thread
    #pragma unroll
    for (int i = 0; i < 4; i++) {
        int idx = tid + i * 256;
        if (i < 2) {
            int r = idx >> 2, c = idx & 3;
            CP_ASYNC16(stage + (uint32_t)(r * (RS*2) + c * 16),
                       Ab + (size_t)r * KT + k0 + c * 8);
        } else {
            int j = idx - 512;
            int r = j >> 2, c = j & 3;
            CP_ASYNC16(stage + ST_A + (uint32_t)(r * (RS*2) + c * 16),
                       Bb + (size_t)r * KT + k0 + c * 8);
        }
    }
}

__device__ __forceinline__ float gelu_exact(float v) {
    return 0.5f * v * (1.0f + erff(v * 0.70710678118654752f));
}

// ---------------- HMMA GEMM: C[M,1024] = A'[M,3072] @ B'[1024,3072]^T ----------------
// EPI: 0 = +bias, 1 = +bias+GELU, 2 = +bias+residual
template<int EPI>
__global__ void __launch_bounds__(256, 1)
gemm_tc(const __nv_bfloat16* __restrict__ Aq, const __nv_bfloat16* __restrict__ Bq,
        const float* __restrict__ bias, const float* __restrict__ Rres, float* __restrict__ C)
{
    extern __shared__ __align__(128) char smem[];
    const uint32_t sb = smem_u32(smem);
    const int tid = threadIdx.x;
    const int wid = tid >> 5, lane = tid & 31;
    const int wm = wid >> 2, wn = wid & 3;            // 2 x 4 warp grid, 64x32 warp tile
    const int bm = blockIdx.y * TILE_M;
    const int bn = blockIdx.x * TILE_N;

    const __nv_bfloat16* Abase = Aq + (size_t)bm * KT;
    const __nv_bfloat16* Bbase = Bq + (size_t)bn * KT;

    // per-lane ldmatrix base offsets (bytes), k-step adds ks*32
    const int lr = lane & 15, lc = lane >> 4;         // row-in-16, 8-col segment
    uint32_t aoff[4], boff[2];
    #pragma unroll
    for (int i = 0; i < 4; i++)
        aoff[i] = (uint32_t)(((wm * 64 + i * 16 + lr) * RS + lc * 8) * 2);
    #pragma unroll
    for (int j = 0; j < 2; j++)
        boff[j] = (uint32_t)(ST_A + ((wn * 32 + j * 16 + lr) * RS + lc * 8) * 2);

    float acc[16][4];
    #pragma unroll
    for (int t = 0; t < 16; t++)
        #pragma unroll
        for (int q = 0; q < 4; q++) acc[t][q] = 0.f;

    // prologue: fill 3 stages
    #pragma unroll
    for (int s = 0; s < 3; s++) { load_stage(sb, Abase, Bbase, s, s, tid); CP_COMMIT(); }

    for (int it = 0; it < NIT; it++) {
        const int slot = it & 3;
        CP_WAIT2();
        __syncthreads();
        if (it + 3 < NIT) load_stage(sb, Abase, Bbase, (it + 3) & 3, it + 3, tid);
        CP_COMMIT();

        const uint32_t st = sb + slot * STG;
        #pragma unroll
        for (int ks = 0; ks < 2; ks++) {
            uint32_t a[4][4], b[2][4];
            #pragma unroll
            for (int i = 0; i < 4; i++)
                ldm_x4(a[i][0], a[i][1], a[i][2], a[i][3], st + aoff[i] + ks * 32);
            #pragma unroll
            for (int j = 0; j < 2; j++)
                ldm_x4(b[j][0], b[j][1], b[j][2], b[j][3], st + boff[j] + ks * 32);
            #pragma unroll
            for (int i = 0; i < 4; i++) {
                #pragma unroll
                for (int j = 0; j < 2; j++) {
                    // n8 tile 2j:   {b0, b2};  n8 tile 2j+1: {b1, b3}
                    mma16816(acc[i*4 + 2*j][0], acc[i*4 + 2*j][1], acc[i*4 + 2*j][2], acc[i*4 + 2*j][3],
                             a[i][0], a[i][1], a[i][2], a[i][3], b[j][0], b[j][2]);
                    mma16816(acc[i*4 + 2*j+1][0], acc[i*4 + 2*j+1][1], acc[i*4 + 2*j+1][2], acc[i*4 + 2*j+1][3],
                             a[i][0], a[i][1], a[i][2], a[i][3], b[j][1], b[j][3]);
                }
            }
        }
    }

    // epilogue from registers: rows lane>>2 (+8), col pairs (lane&3)*2
    const int g = lane >> 2, t4 = (lane & 3) * 2;
    #pragma unroll
    for (int i = 0; i < 4; i++) {
        #pragma unroll
        for (int j = 0; j < 4; j++) {
            const int col = bn + wn * 32 + j * 8 + t4;
            const float bx = bias[col], by = bias[col + 1];
            #pragma unroll
            for (int h = 0; h < 2; h++) {
                const int row = bm + wm * 64 + i * 16 + g + h * 8;
                float vx = acc[i*4 + j][h*2 + 0] + bx;
                float vy = acc[i*4 + j][h*2 + 1] + by;
                if (EPI == 1) { vx = gelu_exact(vx); vy = gelu_exact(vy); }
                if (EPI == 2) {
                    const float2 rv = *(const float2*)&Rres[(size_t)row * ND + col];
                    vx += rv.x; vy += rv.y;
                }
                *(float2*)&C[(size_t)row * ND + col] = make_float2(vx, vy);
            }
        }
    }
}

// ---------------- rmsnorm ----------------
__global__ void rmsnorm_k(const float* __restrict__ x, const float* __restrict__ w,
                          float* __restrict__ y, int residual)
{
    int row = blockIdx.x;
    int tid = threadIdx.x;
    const float4* xr = (const float4*)(x + (size_t)row * 1024);
    float4 v = xr[tid];
    float ss = v.x*v.x + v.y*v.y + v.z*v.z + v.w*v.w;
    #pragma unroll
    for (int o = 16; o > 0; o >>= 1) ss += __shfl_xor_sync(0xffffffffu, ss, o);
    __shared__ float sp[8];
    __shared__ float sscale;
    if ((tid & 31) == 0) sp[tid >> 5] = ss;
    __syncthreads();
    if (tid == 0) {
        float s = 0.f;
        #pragma unroll
        for (int i = 0; i < 8; i++) s += sp[i];
        sscale = rsqrtf(s * (1.0f/1024.0f) + EPSF);
    }
    __syncthreads();
    float sc = sscale;
    float4 wv = ((const float4*)w)[tid];
    float4 o;
    o.x = v.x * sc * wv.x; o.y = v.y * sc * wv.y;
    o.z = v.z * sc * wv.z; o.w = v.w * sc * wv.w;
    if (residual) { o.x += v.x; o.y += v.y; o.z += v.z; o.w += v.w; }
    ((float4*)(y + (size_t)row * 1024))[tid] = o;
}

// ---------------- per-position differential linear attention ----------------
__global__ void attn_k(const float* __restrict__ Q, const float* __restrict__ K,
                       const float* __restrict__ V, const float* __restrict__ lp,
                       const float* __restrict__ g2, float* __restrict__ out)
{
    __shared__ float sQ[1024], sK[1024], sV[1024];
    __shared__ float skv[64 * 64];
    __shared__ float sA[1024];
    __shared__ float sS[16];
    int pos = blockIdx.x, tid = threadIdx.x;
    size_t base = (size_t)pos * 1024;

    for (int i = tid; i < 1024; i += 256) {
        float q = Q[base + i], k = K[base + i];
        sQ[i] = (q > 0.f) ? q : expm1f(q);
        sK[i] = (k > 0.f) ? k : expm1f(k);
        sV[i] = V[base + i];
    }
    __syncthreads();

    for (int idx = tid; idx < 4096; idx += 256) {
        int d = idx >> 6, e = idx & 63;
        float s = 0.f;
        #pragma unroll
        for (int h = 0; h < 16; h++) s += sK[h * 64 + d] * sV[h * 64 + e];
        skv[idx] = s * SCALE_ATT;
    }
    __syncthreads();

    float lam = expf(lp[0] * lp[1]) - expf(lp[2] * lp[3]) + LAM_INIT;

    for (int idx = tid; idx < 1024; idx += 256) {
        int h = idx >> 6, e = idx & 63;
        float s1 = 0.f, s2 = 0.f;
        #pragma unroll
        for (int d = 0; d < 32; d++) {
            s1 += sQ[h * 64 + d]      * skv[d * 64 + e];
            s2 += sQ[h * 64 + 32 + d] * skv[(32 + d) * 64 + e];
        }
        sA[idx] = s1 - lam * s2;
    }
    __syncthreads();

    if (tid < 16) {
        float ss = 0.f;
        #pragma unroll
        for (int e = 0; e < 64; e++) { float v = sA[tid * 64 + e]; ss += v * v; }
        sS[tid] = rsqrtf(ss * (1.0f/64.0f) + EPSF) * ONE_MINUS_LAM_INIT;
    }
    __syncthreads();

    for (int idx = tid; idx < 1024; idx += 256) {
        int h = idx >> 6, e = idx & 63;
        out[base + idx] = sA[idx] * sS[h] * g2[e];
    }
}

// ============================================================
extern "C" void kernel_launch(void* const* d_in, const int* in_sizes, int n_in,
                              void* d_out, int out_size)
{
    const float* x   = (const float*)d_in[0];
    const float* Wq  = (const float*)d_in[1];
    const float* bq  = (const float*)d_in[2];
    const float* Wk  = (const float*)d_in[3];
    const float* bk  = (const float*)d_in[4];
    const float* Wv  = (const float*)d_in[5];
    const float* bv  = (const float*)d_in[6];
    const float* lp  = (const float*)d_in[7];
    const float* g1  = (const float*)d_in[8];
    const float* g2  = (const float*)d_in[9];
    const float* g3  = (const float*)d_in[10];
    const float* Wf1 = (const float*)d_in[11];
    const float* bf1 = (const float*)d_in[12];
    const float* Wf2 = (const float*)d_in[13];
    const float* bf2 = (const float*)d_in[14];
    float* out = (float*)d_out;

    float *xn, *Qp, *Kp, *Vp, *yp, *hp;
    __nv_bfloat16 *Ab, *Wb;
    cudaGetSymbolAddress((void**)&xn, g_xn);
    cudaGetSymbolAddress((void**)&Qp, g_Q);
    cudaGetSymbolAddress((void**)&Kp, g_K);
    cudaGetSymbolAddress((void**)&Vp, g_V);
    cudaGetSymbolAddress((void**)&yp, g_y);
    cudaGetSymbolAddress((void**)&hp, g_h);
    cudaGetSymbolAddress((void**)&Ab, g_Ab);
    cudaGetSymbolAddress((void**)&Wb, g_Wb);

    cudaFuncSetAttribute(gemm_tc<0>, cudaFuncAttributeMaxDynamicSharedMemorySize, SMEM_DYN);
    cudaFuncSetAttribute(gemm_tc<1>, cudaFuncAttributeMaxDynamicSharedMemorySize, SMEM_DYN);
    cudaFuncSetAttribute(gemm_tc<2>, cudaFuncAttributeMaxDynamicSharedMemorySize, SMEM_DYN);

    dim3 gg(ND / TILE_N, M_TOT / TILE_M);   // (8, 64)

    rmsnorm_k<<<M_TOT, 256>>>(x, g1, xn, 0);
    cvt3_k<<<M_TOT, 256>>>(xn, Ab);

    cvt3w_k<<<ND, 256>>>(Wq, Wb);
    gemm_tc<0><<<gg, 256, SMEM_DYN>>>(Ab, Wb, bq, nullptr, Qp);
    cvt3w_k<<<ND, 256>>>(Wk, Wb);
    gemm_tc<0><<<gg, 256, SMEM_DYN>>>(Ab, Wb, bk, nullptr, Kp);
    cvt3w_k<<<ND, 256>>>(Wv, Wb);
    gemm_tc<0><<<gg, 256, SMEM_DYN>>>(Ab, Wb, bv, nullptr, Vp);

    attn_k<<<M_TOT, 256>>>(Qp, Kp, Vp, lp, g2, xn);          // xn reused as raw attn
    rmsnorm_k<<<M_TOT, 256>>>(xn, g3, yp, 1);                // y = rmsnorm(attn)*g3 + attn

    cvt3_k<<<M_TOT, 256>>>(yp, Ab);
    cvt3w_k<<<ND, 256>>>(Wf1, Wb);
    gemm_tc<1><<<gg, 256, SMEM_DYN>>>(Ab, Wb, bf1, nullptr, hp);

    cvt3_k<<<M_TOT, 256>>>(hp, Ab);
    cvt3w_k<<<ND, 256>>>(Wf2, Wb);
    gemm_tc<2><<<gg, 256, SMEM_DYN>>>(Ab, Wb, bf2, yp, out);
}

// round 5
// speedup vs baseline: 2.1757x; 1.5103x over previous
#include <cuda_runtime.h>
#include <cuda_fp16.h>
#include <math.h>
#include <stdint.h>

// ---------------- problem constants ----------------
#define M_TOT 8192
#define KD    1024
#define ND    1024
#define KA    2048                 // doubled K: [A_hi | A_lo] fp16, W replicated hi
#define EPSF  1.1920929e-07f
#define LAM_INIT 0.2f
#define ONE_MINUS_LAM_INIT 0.8f
#define SCALE_ATT 0.044194173824159216f

// ---------------- GEMM tiling ----------------
#define TILE_M 128
#define TILE_N 128
#define KC     32                  // K per stage
#define NIT    (KA/KC)             // 64
#define RS     40                  // smem row stride in halves (32 + 8 pad) = 80B
#define ST_A   (128*RS*2)          // 10240 B
#define STG    (2*ST_A)            // 20480 B per stage (A+B)
#define STAGES 3
#define SMEM_DYN (STAGES*STG)      // 61440 -> 2 CTAs/SM

// ---------------- scratch (__device__ globals; no allocs allowed) ----------------
__device__ float g_Q [(size_t)M_TOT * ND];
__device__ float g_K [(size_t)M_TOT * ND];
__device__ float g_V [(size_t)M_TOT * ND];
__device__ float g_at[(size_t)M_TOT * ND];     // attention output
__device__ float g_y [(size_t)M_TOT * ND];     // rmsnorm3 + residual
__device__ __align__(128) __half g_A1[(size_t)M_TOT * KA];   // 32MB split activations
__device__ __align__(128) __half g_A2[(size_t)M_TOT * KA];   // 32MB split h
__device__ __align__(128) __half g_W [(size_t)ND * KD];      // 2MB weight hi

// ---------------- PTX helpers (base ISA only) ----------------
__device__ __forceinline__ uint32_t smem_u32(const void* p) {
    uint32_t a;
    asm("{ .reg .u64 t; cvta.to.shared.u64 t, %1; cvt.u32.u64 %0, t; }" : "=r"(a) : "l"(p));
    return a;
}
#define CP_ASYNC16(dst, src) \
    asm volatile("cp.async.cg.shared.global [%0], [%1], 16;" :: "r"(dst), "l"(src) : "memory")
#define CP_COMMIT() asm volatile("cp.async.commit_group;" ::: "memory")
#define CP_WAIT1()  asm volatile("cp.async.wait_group 1;" ::: "memory")

__device__ __forceinline__ void ldm_x4(uint32_t& r0, uint32_t& r1, uint32_t& r2, uint32_t& r3,
                                       uint32_t addr) {
    asm volatile("ldmatrix.sync.aligned.m8n8.x4.shared.b16 {%0,%1,%2,%3}, [%4];"
                 : "=r"(r0), "=r"(r1), "=r"(r2), "=r"(r3) : "r"(addr));
}
__device__ __forceinline__ void mma16816(float& c0, float& c1, float& c2, float& c3,
                                         uint32_t a0, uint32_t a1, uint32_t a2, uint32_t a3,
                                         uint32_t b0, uint32_t b1) {
    asm volatile("mma.sync.aligned.m16n8k16.row.col.f32.f16.f16.f32 "
                 "{%0,%1,%2,%3}, {%4,%5,%6,%7}, {%8,%9}, {%0,%1,%2,%3};"
                 : "+f"(c0), "+f"(c1), "+f"(c2), "+f"(c3)
                 : "r"(a0), "r"(a1), "r"(a2), "r"(a3), "r"(b0), "r"(b1));
}

__device__ __forceinline__ void split_store(__half* base, size_t row, int col,
                                            float vx, float vy) {
    __half hx = __float2half_rn(vx), hy = __float2half_rn(vy);
    __half lx = __float2half_rn(vx - __half2float(hx));
    __half ly = __float2half_rn(vy - __half2float(hy));
    __half2 hh; hh.x = hx; hh.y = hy;
    __half2 ll; ll.x = lx; ll.y = ly;
    *(__half2*)&base[row * KA + col]        = hh;
    *(__half2*)&base[row * KA + 1024 + col] = ll;
}

// ---------------- weight hi convert: fp32 [1024,1024] -> fp16 ----------------
__global__ void cvtw_k(const float* __restrict__ X, __half* __restrict__ Y)
{
    size_t i4 = (size_t)blockIdx.x * 256 + threadIdx.x;
    float4 v = ((const float4*)X)[i4];
    __half2 a; a.x = __float2half_rn(v.x); a.y = __float2half_rn(v.y);
    __half2 b; b.x = __float2half_rn(v.z); b.y = __float2half_rn(v.w);
    uint2 o; o.x = *(uint32_t*)&a; o.y = *(uint32_t*)&b;
    ((uint2*)Y)[i4] = o;
}

// ---------------- stage loader: cp.async 16B chunks, padded rows ----------------
__device__ __forceinline__ void load_stage(uint32_t stage, const __half* Ab,
                                           const __half* Bb, int kiter, int tid)
{
    const int k0 = kiter * KC;
    const int k0b = k0 & 1023;          // W replicated: wrap into [0,1024)
    #pragma unroll
    for (int i = 0; i < 4; i++) {
        int idx = tid + i * 256;
        if (i < 2) {
            int r = idx >> 2, c = idx & 3;
            CP_ASYNC16(stage + (uint32_t)(r * (RS*2) + c * 16),
                       Ab + (size_t)r * KA + k0 + c * 8);
        } else {
            int j = idx - 512;
            int r = j >> 2, c = j & 3;
            CP_ASYNC16(stage + ST_A + (uint32_t)(r * (RS*2) + c * 16),
                       Bb + (size_t)r * KD + k0b + c * 8);
        }
    }
}

__device__ __forceinline__ float gelu_exact(float v) {
    return 0.5f * v * (1.0f + erff(v * 0.70710678118654752f));
}

// ---------------- HMMA GEMM: C[M,1024] = A'[M,2048] @ [W_hi|W_hi]^T ----------------
// EPI: 0 = +bias -> fp32 C ; 1 = +bias+GELU -> fp16 split C2 ; 2 = +bias+residual -> fp32 C
template<int EPI>
__global__ void __launch_bounds__(256, 2)
gemm_tc(const __half* __restrict__ Aq, const __half* __restrict__ Bq,
        const float* __restrict__ bias, const float* __restrict__ Rres,
        float* __restrict__ C, __half* __restrict__ C2)
{
    extern __shared__ __align__(128) char smem[];
    const uint32_t sb = smem_u32(smem);
    const int tid = threadIdx.x;
    const int wid = tid >> 5, lane = tid & 31;
    const int wm = wid >> 2, wn = wid & 3;            // 2 x 4 warp grid, 64x32 warp tile
    const int bm = blockIdx.y * TILE_M;
    const int bn = blockIdx.x * TILE_N;

    const __half* Abase = Aq + (size_t)bm * KA;
    const __half* Bbase = Bq + (size_t)bn * KD;

    const int lr = lane & 15, lc = lane >> 4;
    uint32_t aoff[4], boff[2];
    #pragma unroll
    for (int i = 0; i < 4; i++)
        aoff[i] = (uint32_t)(((wm * 64 + i * 16 + lr) * RS + lc * 8) * 2);
    #pragma unroll
    for (int j = 0; j < 2; j++)
        boff[j] = (uint32_t)(ST_A + ((wn * 32 + j * 16 + lr) * RS + lc * 8) * 2);

    float acc[16][4];
    #pragma unroll
    for (int t = 0; t < 16; t++)
        #pragma unroll
        for (int q = 0; q < 4; q++) acc[t][q] = 0.f;

    // prologue: 2 stages in flight
    load_stage(sb,           Abase, Bbase, 0, tid); CP_COMMIT();
    load_stage(sb + STG,     Abase, Bbase, 1, tid); CP_COMMIT();

    int slot = 0, slot2 = 2;      // slot = it%3, slot2 = (it+2)%3
    for (int it = 0; it < NIT; it++) {
        CP_WAIT1();
        __syncthreads();
        if (it + 2 < NIT) load_stage(sb + slot2 * STG, Abase, Bbase, it + 2, tid);
        CP_COMMIT();

        const uint32_t st = sb + slot * STG;
        #pragma unroll
        for (int ks = 0; ks < 2; ks++) {
            uint32_t a[4][4], b[2][4];
            #pragma unroll
            for (int i = 0; i < 4; i++)
                ldm_x4(a[i][0], a[i][1], a[i][2], a[i][3], st + aoff[i] + ks * 32);
            #pragma unroll
            for (int j = 0; j < 2; j++)
                ldm_x4(b[j][0], b[j][1], b[j][2], b[j][3], st + boff[j] + ks * 32);
            #pragma unroll
            for (int i = 0; i < 4; i++) {
                #pragma unroll
                for (int j = 0; j < 2; j++) {
                    mma16816(acc[i*4 + 2*j][0], acc[i*4 + 2*j][1], acc[i*4 + 2*j][2], acc[i*4 + 2*j][3],
                             a[i][0], a[i][1], a[i][2], a[i][3], b[j][0], b[j][2]);
                    mma16816(acc[i*4 + 2*j+1][0], acc[i*4 + 2*j+1][1], acc[i*4 + 2*j+1][2], acc[i*4 + 2*j+1][3],
                             a[i][0], a[i][1], a[i][2], a[i][3], b[j][1], b[j][3]);
                }
            }
        }
        slot  = (slot  == 2) ? 0 : slot + 1;
        slot2 = (slot2 == 2) ? 0 : slot2 + 1;
    }

    // epilogue from registers
    const int g = lane >> 2, t4 = (lane & 3) * 2;
    #pragma unroll
    for (int i = 0; i < 4; i++) {
        #pragma unroll
        for (int j = 0; j < 4; j++) {
            const int col = bn + wn * 32 + j * 8 + t4;
            const float bx = bias[col], by = bias[col + 1];
            #pragma unroll
            for (int h = 0; h < 2; h++) {
                const size_t row = (size_t)(bm + wm * 64 + i * 16 + g + h * 8);
                float vx = acc[i*4 + j][h*2 + 0] + bx;
                float vy = acc[i*4 + j][h*2 + 1] + by;
                if (EPI == 1) {
                    vx = gelu_exact(vx); vy = gelu_exact(vy);
                    split_store(C2, row, col, vx, vy);
                } else {
                    if (EPI == 2) {
                        const float2 rv = *(const float2*)&Rres[row * ND + col];
                        vx += rv.x; vy += rv.y;
                    }
                    *(float2*)&C[row * ND + col] = make_float2(vx, vy);
                }
            }
        }
    }
}

// ---------------- rmsnorm: MODE 0 -> split only; MODE 1 -> fp32(+x) and split ----------------
template<int MODE>
__global__ void rmsnorm_k(const float* __restrict__ x, const float* __restrict__ w,
                          float* __restrict__ y, __half* __restrict__ ysplit)
{
    int row = blockIdx.x;
    int tid = threadIdx.x;                          // 256 threads x 4 floats
    const float4* xr = (const float4*)(x + (size_t)row * 1024);
    float4 v = xr[tid];
    float ss = v.x*v.x + v.y*v.y + v.z*v.z + v.w*v.w;
    #pragma unroll
    for (int o = 16; o > 0; o >>= 1) ss += __shfl_xor_sync(0xffffffffu, ss, o);
    __shared__ float sp[8];
    __shared__ float sscale;
    if ((tid & 31) == 0) sp[tid >> 5] = ss;
    __syncthreads();
    if (tid == 0) {
        float s = 0.f;
        #pragma unroll
        for (int i = 0; i < 8; i++) s += sp[i];
        sscale = rsqrtf(s * (1.0f/1024.0f) + EPSF);
    }
    __syncthreads();
    float sc = sscale;
    float4 wv = ((const float4*)w)[tid];
    float4 o;
    o.x = v.x * sc * wv.x; o.y = v.y * sc * wv.y;
    o.z = v.z * sc * wv.z; o.w = v.w * sc * wv.w;
    if (MODE == 1) {
        o.x += v.x; o.y += v.y; o.z += v.z; o.w += v.w;
        ((float4*)(y + (size_t)row * 1024))[tid] = o;
    }
    split_store(ysplit, (size_t)row, tid * 4,     o.x, o.y);
    split_store(ysplit, (size_t)row, tid * 4 + 2, o.z, o.w);
}

// ---------------- per-position differential linear attention (float4 LDS) ----------------
__global__ void attn_k(const float* __restrict__ Q, const float* __restrict__ K,
                       const float* __restrict__ V, const float* __restrict__ lp,
                       const float* __restrict__ g2, float* __restrict__ out)
{
    __shared__ float sQ[1024], sK[1024], sV[1024];
    __shared__ float skv[64 * 64];
    __shared__ float sA[1024];
    __shared__ float sS[16];
    int pos = blockIdx.x, tid = threadIdx.x;
    size_t base = (size_t)pos * 1024;

    for (int i = tid; i < 1024; i += 256) {
        float q = Q[base + i], k = K[base + i];
        sQ[i] = (q > 0.f) ? q : expm1f(q);
        sK[i] = (k > 0.f) ? k : expm1f(k);
        sV[i] = V[base + i];
    }
    __syncthreads();

    // kv[d][e] = SCALE * sum_h phi(K)[h,d] * V[h,e]; float4 over e (64 d x 16 e4 = 1024 items)
    for (int idx = tid; idx < 1024; idx += 256) {
        int d = idx >> 4, e4 = (idx & 15) * 4;
        float4 s = make_float4(0.f, 0.f, 0.f, 0.f);
        #pragma unroll
        for (int h = 0; h < 16; h++) {
            float kd = sK[h * 64 + d];
            float4 vv = *(const float4*)&sV[h * 64 + e4];
            s.x += kd * vv.x; s.y += kd * vv.y; s.z += kd * vv.z; s.w += kd * vv.w;
        }
        s.x *= SCALE_ATT; s.y *= SCALE_ATT; s.z *= SCALE_ATT; s.w *= SCALE_ATT;
        *(float4*)&skv[d * 64 + e4] = s;
    }
    __syncthreads();

    float lam = expf(lp[0] * lp[1]) - expf(lp[2] * lp[3]) + LAM_INIT;

    // a[h][e] float4 over e: 16 h x 16 e4 = 256 items  (round-4 bug was bound 1024 here)
    for (int idx = tid; idx < 256; idx += 256) {
        int h = idx >> 4, e4 = (idx & 15) * 4;
        float4 s1 = make_float4(0.f, 0.f, 0.f, 0.f);
        float4 s2 = make_float4(0.f, 0.f, 0.f, 0.f);
        #pragma unroll
        for (int d = 0; d < 32; d++) {
            float q1 = sQ[h * 64 + d], q2 = sQ[h * 64 + 32 + d];
            float4 f1 = *(const float4*)&skv[d * 64 + e4];
            float4 f2 = *(const float4*)&skv[(32 + d) * 64 + e4];
            s1.x += q1 * f1.x; s1.y += q1 * f1.y; s1.z += q1 * f1.z; s1.w += q1 * f1.w;
            s2.x += q2 * f2.x; s2.y += q2 * f2.y; s2.z += q2 * f2.z; s2.w += q2 * f2.w;
        }
        float4 a;
        a.x = s1.x - lam * s2.x; a.y = s1.y - lam * s2.y;
        a.z = s1.z - lam * s2.z; a.w = s1.w - lam * s2.w;
        *(float4*)&sA[h * 64 + e4] = a;
    }
    __syncthreads();

    if (tid < 16) {
        float ss = 0.f;
        #pragma unroll
        for (int e = 0; e < 64; e++) { float v = sA[tid * 64 + e]; ss += v * v; }
        sS[tid] = rsqrtf(ss * (1.0f/64.0f) + EPSF) * ONE_MINUS_LAM_INIT;
    }
    __syncthreads();

    for (int idx = tid; idx < 1024; idx += 256) {
        int h = idx >> 6, e = idx & 63;
        out[base + idx] = sA[idx] * sS[h] * g2[e];
    }
}

// ============================================================
extern "C" void kernel_launch(void* const* d_in, const int* in_sizes, int n_in,
                              void* d_out, int out_size)
{
    const float* x   = (const float*)d_in[0];
    const float* Wq  = (const float*)d_in[1];
    const float* bq  = (const float*)d_in[2];
    const float* Wk  = (const float*)d_in[3];
    const float* bk  = (const float*)d_in[4];
    const float* Wv  = (const float*)d_in[5];
    const float* bv  = (const float*)d_in[6];
    const float* lp  = (const float*)d_in[7];
    const float* g1  = (const float*)d_in[8];
    const float* g2  = (const float*)d_in[9];
    const float* g3  = (const float*)d_in[10];
    const float* Wf1 = (const float*)d_in[11];
    const float* bf1 = (const float*)d_in[12];
    const float* Wf2 = (const float*)d_in[13];
    const float* bf2 = (const float*)d_in[14];
    float* out = (float*)d_out;

    float *Qp, *Kp, *Vp, *ap, *yp;
    __half *A1, *A2, *Wb;
    cudaGetSymbolAddress((void**)&Qp, g_Q);
    cudaGetSymbolAddress((void**)&Kp, g_K);
    cudaGetSymbolAddress((void**)&Vp, g_V);
    cudaGetSymbolAddress((void**)&ap, g_at);
    cudaGetSymbolAddress((void**)&yp, g_y);
    cudaGetSymbolAddress((void**)&A1, g_A1);
    cudaGetSymbolAddress((void**)&A2, g_A2);
    cudaGetSymbolAddress((void**)&Wb, g_W);

    cudaFuncSetAttribute(gemm_tc<0>, cudaFuncAttributeMaxDynamicSharedMemorySize, SMEM_DYN);
    cudaFuncSetAttribute(gemm_tc<1>, cudaFuncAttributeMaxDynamicSharedMemorySize, SMEM_DYN);
    cudaFuncSetAttribute(gemm_tc<2>, cudaFuncAttributeMaxDynamicSharedMemorySize, SMEM_DYN);

    dim3 gg(ND / TILE_N, M_TOT / TILE_M);   // (8, 64)

    rmsnorm_k<0><<<M_TOT, 256>>>(x, g1, nullptr, A1);

    cvtw_k<<<1024, 256>>>(Wq, Wb);
    gemm_tc<0><<<gg, 256, SMEM_DYN>>>(A1, Wb, bq, nullptr, Qp, nullptr);
    cvtw_k<<<1024, 256>>>(Wk, Wb);
    gemm_tc<0><<<gg, 256, SMEM_DYN>>>(A1, Wb, bk, nullptr, Kp, nullptr);
    cvtw_k<<<1024, 256>>>(Wv, Wb);
    gemm_tc<0><<<gg, 256, SMEM_DYN>>>(A1, Wb, bv, nullptr, Vp, nullptr);

    attn_k<<<M_TOT, 256>>>(Qp, Kp, Vp, lp, g2, ap);
    rmsnorm_k<1><<<M_TOT, 256>>>(ap, g3, yp, A1);            // yp = rmsnorm*g3 + attn, + split

    cvtw_k<<<1024, 256>>>(Wf1, Wb);
    gemm_tc<1><<<gg, 256, SMEM_DYN>>>(A1, Wb, bf1, nullptr, nullptr, A2);   // h split direct

    cvtw_k<<<1024, 256>>>(Wf2, Wb);
    gemm_tc<2><<<gg, 256, SMEM_DYN>>>(A2, Wb, bf2, yp, out, nullptr);
}

// round 6
// speedup vs baseline: 2.5416x; 1.1682x over previous
#include <cuda_runtime.h>
#include <cuda_fp16.h>
#include <math.h>
#include <stdint.h>

// ---------------- problem constants ----------------
#define M_TOT 8192
#define KD    1024
#define ND    1024
#define KA    2048                 // [A_hi | A_lo] fp16, W replicated hi
#define EPSF  1.1920929e-07f
#define LAM_INIT 0.2f
#define ONE_MINUS_LAM_INIT 0.8f
#define SCALE_ATT 0.044194173824159216f

// ---------------- GEMM tiling ----------------
#define TILE_M 128
#define TILE_N 128
#define KC     32                  // K per stage
#define NIT    (KA/KC)             // 64
#define RS     40                  // smem row stride in halves (32 + 8 pad) = 80B
#define ST_A   (128*RS*2)          // 10240 B
#define STG    (2*ST_A)            // 20480 B per stage (A+B)
#define STAGES 4
#define SMEM_DYN (STAGES*STG)      // 81920 -> still 2 CTAs/SM (163KB < 228KB)

#define WMAT   ((size_t)1048576)   // elems per weight matrix

// ---------------- scratch (__device__ globals; no allocs allowed) ----------------
__device__ float g_Q [(size_t)M_TOT * ND];
__device__ float g_K [(size_t)M_TOT * ND];
__device__ float g_V [(size_t)M_TOT * ND];
__device__ float g_y [(size_t)M_TOT * ND];     // rmsnorm3 + residual (fp32)
__device__ __align__(128) __half g_A1[(size_t)M_TOT * KA];   // 32MB split activations
__device__ __align__(128) __half g_A2[(size_t)M_TOT * KA];   // 32MB split h
__device__ __align__(128) __half g_W [5 * WMAT];             // 10MB: Wq|Wk|Wv|Wf1|Wf2 (hi)

// ---------------- PTX helpers (base ISA only) ----------------
__device__ __forceinline__ uint32_t smem_u32(const void* p) {
    uint32_t a;
    asm("{ .reg .u64 t; cvta.to.shared.u64 t, %1; cvt.u32.u64 %0, t; }" : "=r"(a) : "l"(p));
    return a;
}
#define CP_ASYNC16(dst, src) \
    asm volatile("cp.async.cg.shared.global [%0], [%1], 16;" :: "r"(dst), "l"(src) : "memory")
#define CP_COMMIT() asm volatile("cp.async.commit_group;" ::: "memory")
#define CP_WAIT2()  asm volatile("cp.async.wait_group 2;" ::: "memory")

__device__ __forceinline__ void ldm_x4(uint32_t& r0, uint32_t& r1, uint32_t& r2, uint32_t& r3,
                                       uint32_t addr) {
    asm volatile("ldmatrix.sync.aligned.m8n8.x4.shared.b16 {%0,%1,%2,%3}, [%4];"
                 : "=r"(r0), "=r"(r1), "=r"(r2), "=r"(r3) : "r"(addr));
}
__device__ __forceinline__ void mma16816(float& c0, float& c1, float& c2, float& c3,
                                         uint32_t a0, uint32_t a1, uint32_t a2, uint32_t a3,
                                         uint32_t b0, uint32_t b1) {
    asm volatile("mma.sync.aligned.m16n8k16.row.col.f32.f16.f16.f32 "
                 "{%0,%1,%2,%3}, {%4,%5,%6,%7}, {%8,%9}, {%0,%1,%2,%3};"
                 : "+f"(c0), "+f"(c1), "+f"(c2), "+f"(c3)
                 : "r"(a0), "r"(a1), "r"(a2), "r"(a3), "r"(b0), "r"(b1));
}

__device__ __forceinline__ void split_store(__half* base, size_t row, int col,
                                            float vx, float vy) {
    __half hx = __float2half_rn(vx), hy = __float2half_rn(vy);
    __half lx = __float2half_rn(vx - __half2float(hx));
    __half ly = __float2half_rn(vy - __half2float(hy));
    __half2 hh; hh.x = hx; hh.y = hy;
    __half2 ll; ll.x = lx; ll.y = ly;
    *(__half2*)&base[row * KA + col]        = hh;
    *(__half2*)&base[row * KA + 1024 + col] = ll;
}

__device__ __forceinline__ float gelu_exact(float v) {
    return 0.5f * v * (1.0f + erff(v * 0.70710678118654752f));
}

// ---------------- all-weights convert: 5x fp32 [1024,1024] -> fp16 hi, concatenated ----------------
__global__ void cvtw_all(const float* __restrict__ w0, const float* __restrict__ w1,
                         const float* __restrict__ w2, const float* __restrict__ w3,
                         const float* __restrict__ w4, __half* __restrict__ Y)
{
    size_t i4 = (size_t)blockIdx.x * 256 + threadIdx.x;   // float4 index, 5*262144 total
    int m = (int)(i4 >> 18);
    const float* src = (m == 0) ? w0 : (m == 1) ? w1 : (m == 2) ? w2 : (m == 3) ? w3 : w4;
    float4 v = ((const float4*)src)[i4 & 262143];
    __half2 a; a.x = __float2half_rn(v.x); a.y = __float2half_rn(v.y);
    __half2 b; b.x = __float2half_rn(v.z); b.y = __float2half_rn(v.w);
    uint2 o; o.x = *(uint32_t*)&a; o.y = *(uint32_t*)&b;
    ((uint2*)Y)[i4] = o;
}

// ---------------- stage loader: cp.async 16B chunks, padded rows ----------------
__device__ __forceinline__ void load_stage(uint32_t stage, const __half* Ab,
                                           const __half* Bb, int kiter, int tid)
{
    const int k0 = kiter * KC;
    const int k0b = k0 & 1023;          // W replicated: wrap into [0,1024)
    #pragma unroll
    for (int i = 0; i < 4; i++) {
        int idx = tid + i * 256;
        if (i < 2) {
            int r = idx >> 2, c = idx & 3;
            CP_ASYNC16(stage + (uint32_t)(r * (RS*2) + c * 16),
                       Ab + (size_t)r * KA + k0 + c * 8);
        } else {
            int j = idx - 512;
            int r = j >> 2, c = j & 3;
            CP_ASYNC16(stage + ST_A + (uint32_t)(r * (RS*2) + c * 16),
                       Bb + (size_t)r * KD + k0b + c * 8);
        }
    }
}

// ---------------- shared GEMM mainloop (accumulates into acc[16][4]) ----------------
__device__ __forceinline__ void gemm_mainloop(uint32_t sb, const __half* Abase,
                                              const __half* Bbase, int tid,
                                              const uint32_t* aoff, const uint32_t* boff,
                                              float acc[16][4])
{
    load_stage(sb,           Abase, Bbase, 0, tid); CP_COMMIT();
    load_stage(sb + STG,     Abase, Bbase, 1, tid); CP_COMMIT();
    load_stage(sb + 2*STG,   Abase, Bbase, 2, tid); CP_COMMIT();

    for (int it = 0; it < NIT; it++) {
        const int slot = it & 3;
        CP_WAIT2();
        __syncthreads();
        if (it + 3 < NIT) load_stage(sb + ((it + 3) & 3) * STG, Abase, Bbase, it + 3, tid);
        CP_COMMIT();

        const uint32_t st = sb + slot * STG;
        #pragma unroll
        for (int ks = 0; ks < 2; ks++) {
            uint32_t a[4][4], b[2][4];
            #pragma unroll
            for (int i = 0; i < 4; i++)
                ldm_x4(a[i][0], a[i][1], a[i][2], a[i][3], st + aoff[i] + ks * 32);
            #pragma unroll
            for (int j = 0; j < 2; j++)
                ldm_x4(b[j][0], b[j][1], b[j][2], b[j][3], st + boff[j] + ks * 32);
            #pragma unroll
            for (int i = 0; i < 4; i++) {
                #pragma unroll
                for (int j = 0; j < 2; j++) {
                    mma16816(acc[i*4 + 2*j][0], acc[i*4 + 2*j][1], acc[i*4 + 2*j][2], acc[i*4 + 2*j][3],
                             a[i][0], a[i][1], a[i][2], a[i][3], b[j][0], b[j][2]);
                    mma16816(acc[i*4 + 2*j+1][0], acc[i*4 + 2*j+1][1], acc[i*4 + 2*j+1][2], acc[i*4 + 2*j+1][3],
                             a[i][0], a[i][1], a[i][2], a[i][3], b[j][1], b[j][3]);
                }
            }
        }
    }
}

// ---------------- fused QKV GEMM: grid (24, 64); bn selects target matrix ----------------
__global__ void __launch_bounds__(256, 2)
gemm_qkv(const __half* __restrict__ Aq, const __half* __restrict__ Wall,
         const float* __restrict__ bq, const float* __restrict__ bk, const float* __restrict__ bv,
         float* __restrict__ Qp, float* __restrict__ Kp, float* __restrict__ Vp)
{
    extern __shared__ __align__(128) char smem[];
    const uint32_t sb = smem_u32(smem);
    const int tid = threadIdx.x;
    const int wid = tid >> 5, lane = tid & 31;
    const int wm = wid >> 2, wn = wid & 3;
    const int bm = blockIdx.y * TILE_M;
    const int bn = blockIdx.x * TILE_N;            // 0..3071

    const __half* Abase = Aq + (size_t)bm * KA;
    const __half* Bbase = Wall + (size_t)bn * KD;

    const int lr = lane & 15, lc = lane >> 4;
    uint32_t aoff[4], boff[2];
    #pragma unroll
    for (int i = 0; i < 4; i++)
        aoff[i] = (uint32_t)(((wm * 64 + i * 16 + lr) * RS + lc * 8) * 2);
    #pragma unroll
    for (int j = 0; j < 2; j++)
        boff[j] = (uint32_t)(ST_A + ((wn * 32 + j * 16 + lr) * RS + lc * 8) * 2);

    float acc[16][4];
    #pragma unroll
    for (int t = 0; t < 16; t++)
        #pragma unroll
        for (int q = 0; q < 4; q++) acc[t][q] = 0.f;

    gemm_mainloop(sb, Abase, Bbase, tid, aoff, boff, acc);

    const int sel = bn >> 10;
    const float* bias = (sel == 0) ? bq : (sel == 1) ? bk : bv;
    float* C = (sel == 0) ? Qp : (sel == 1) ? Kp : Vp;
    const int cw = bn & 1023;

    const int g = lane >> 2, t4 = (lane & 3) * 2;
    #pragma unroll
    for (int i = 0; i < 4; i++) {
        #pragma unroll
        for (int j = 0; j < 4; j++) {
            const int col = cw + wn * 32 + j * 8 + t4;
            const float bx = bias[col], by = bias[col + 1];
            #pragma unroll
            for (int h = 0; h < 2; h++) {
                const size_t row = (size_t)(bm + wm * 64 + i * 16 + g + h * 8);
                *(float2*)&C[row * ND + col] =
                    make_float2(acc[i*4 + j][h*2 + 0] + bx, acc[i*4 + j][h*2 + 1] + by);
            }
        }
    }
}

// ---------------- FF GEMM: EPI 1 = +bias+GELU -> fp16 split; EPI 2 = +bias+residual -> fp32 ----------------
template<int EPI>
__global__ void __launch_bounds__(256, 2)
gemm_tc(const __half* __restrict__ Aq, const __half* __restrict__ Bq,
        const float* __restrict__ bias, const float* __restrict__ Rres,
        float* __restrict__ C, __half* __restrict__ C2)
{
    extern __shared__ __align__(128) char smem[];
    const uint32_t sb = smem_u32(smem);
    const int tid = threadIdx.x;
    const int wid = tid >> 5, lane = tid & 31;
    const int wm = wid >> 2, wn = wid & 3;
    const int bm = blockIdx.y * TILE_M;
    const int bn = blockIdx.x * TILE_N;

    const __half* Abase = Aq + (size_t)bm * KA;
    const __half* Bbase = Bq + (size_t)bn * KD;

    const int lr = lane & 15, lc = lane >> 4;
    uint32_t aoff[4], boff[2];
    #pragma unroll
    for (int i = 0; i < 4; i++)
        aoff[i] = (uint32_t)(((wm * 64 + i * 16 + lr) * RS + lc * 8) * 2);
    #pragma unroll
    for (int j = 0; j < 2; j++)
        boff[j] = (uint32_t)(ST_A + ((wn * 32 + j * 16 + lr) * RS + lc * 8) * 2);

    float acc[16][4];
    #pragma unroll
    for (int t = 0; t < 16; t++)
        #pragma unroll
        for (int q = 0; q < 4; q++) acc[t][q] = 0.f;

    gemm_mainloop(sb, Abase, Bbase, tid, aoff, boff, acc);

    const int g = lane >> 2, t4 = (lane & 3) * 2;
    #pragma unroll
    for (int i = 0; i < 4; i++) {
        #pragma unroll
        for (int j = 0; j < 4; j++) {
            const int col = bn + wn * 32 + j * 8 + t4;
            const float bx = bias[col], by = bias[col + 1];
            #pragma unroll
            for (int h = 0; h < 2; h++) {
                const size_t row = (size_t)(bm + wm * 64 + i * 16 + g + h * 8);
                float vx = acc[i*4 + j][h*2 + 0] + bx;
                float vy = acc[i*4 + j][h*2 + 1] + by;
                if (EPI == 1) {
                    vx = gelu_exact(vx); vy = gelu_exact(vy);
                    split_store(C2, row, col, vx, vy);
                } else {
                    const float2 rv = *(const float2*)&Rres[row * ND + col];
                    *(float2*)&C[row * ND + col] = make_float2(vx + rv.x, vy + rv.y);
                }
            }
        }
    }
}

// ---------------- rmsnorm (input norm): writes fp16 split only ----------------
__global__ void rmsnorm_k(const float* __restrict__ x, const float* __restrict__ w,
                          __half* __restrict__ ysplit)
{
    int row = blockIdx.x;
    int tid = threadIdx.x;                          // 256 threads x 4 floats
    const float4* xr = (const float4*)(x + (size_t)row * 1024);
    float4 v = xr[tid];
    float ss = v.x*v.x + v.y*v.y + v.z*v.z + v.w*v.w;
    #pragma unroll
    for (int o = 16; o > 0; o >>= 1) ss += __shfl_xor_sync(0xffffffffu, ss, o);
    __shared__ float sp[8];
    __shared__ float sscale;
    if ((tid & 31) == 0) sp[tid >> 5] = ss;
    __syncthreads();
    if (tid == 0) {
        float s = 0.f;
        #pragma unroll
        for (int i = 0; i < 8; i++) s += sp[i];
        sscale = rsqrtf(s * (1.0f/1024.0f) + EPSF);
    }
    __syncthreads();
    float sc = sscale;
    float4 wv = ((const float4*)w)[tid];
    float4 o;
    o.x = v.x * sc * wv.x; o.y = v.y * sc * wv.y;
    o.z = v.z * sc * wv.z; o.w = v.w * sc * wv.w;
    split_store(ysplit, (size_t)row, tid * 4,     o.x, o.y);
    split_store(ysplit, (size_t)row, tid * 4 + 2, o.z, o.w);
}

// ---------------- fused attention + head-rmsnorm(g2) + rmsnorm(g3) + residual + split ----------------
__global__ void attn_fused(const float* __restrict__ Q, const float* __restrict__ K,
                           const float* __restrict__ V, const float* __restrict__ lp,
                           const float* __restrict__ g2, const float* __restrict__ g3,
                           float* __restrict__ yp, __half* __restrict__ ysplit)
{
    __shared__ float sQ[1024], sK[1024], sV[1024];
    __shared__ float skv[64 * 64];
    __shared__ float sA[1024];
    __shared__ float sS[16];
    __shared__ float sp[8];
    __shared__ float sscale;
    int pos = blockIdx.x, tid = threadIdx.x;
    size_t base = (size_t)pos * 1024;

    {   // vectorized load + elu
        float4 q = ((const float4*)(Q + base))[tid];
        float4 k = ((const float4*)(K + base))[tid];
        float4 v = ((const float4*)(V + base))[tid];
        float qe[4] = {q.x, q.y, q.z, q.w}, ke[4] = {k.x, k.y, k.z, k.w};
        #pragma unroll
        for (int j = 0; j < 4; j++) {
            qe[j] = (qe[j] > 0.f) ? qe[j] : expm1f(qe[j]);
            ke[j] = (ke[j] > 0.f) ? ke[j] : expm1f(ke[j]);
        }
        *(float4*)&sQ[tid*4] = make_float4(qe[0], qe[1], qe[2], qe[3]);
        *(float4*)&sK[tid*4] = make_float4(ke[0], ke[1], ke[2], ke[3]);
        *(float4*)&sV[tid*4] = v;
    }
    __syncthreads();

    // kv[d][e] = SCALE * sum_h phi(K)[h,d] * V[h,e]; 64 d x 16 e4 = 1024 items
    for (int idx = tid; idx < 1024; idx += 256) {
        int d = idx >> 4, e4 = (idx & 15) * 4;
        float4 s = make_float4(0.f, 0.f, 0.f, 0.f);
        #pragma unroll
        for (int h = 0; h < 16; h++) {
            float kd = sK[h * 64 + d];
            float4 vv = *(const float4*)&sV[h * 64 + e4];
            s.x += kd * vv.x; s.y += kd * vv.y; s.z += kd * vv.z; s.w += kd * vv.w;
        }
        s.x *= SCALE_ATT; s.y *= SCALE_ATT; s.z *= SCALE_ATT; s.w *= SCALE_ATT;
        *(float4*)&skv[d * 64 + e4] = s;
    }
    __syncthreads();

    float lam = expf(lp[0] * lp[1]) - expf(lp[2] * lp[3]) + LAM_INIT;

    // attn1[h][e]: 16 h x 16 e4 = 256 items
    {
        int idx = tid;
        int h = idx >> 4, e4 = (idx & 15) * 4;
        float4 s1 = make_float4(0.f, 0.f, 0.f, 0.f);
        float4 s2 = make_float4(0.f, 0.f, 0.f, 0.f);
        #pragma unroll
        for (int d = 0; d < 32; d++) {
            float q1 = sQ[h * 64 + d], q2 = sQ[h * 64 + 32 + d];
            float4 f1 = *(const float4*)&skv[d * 64 + e4];
            float4 f2 = *(const float4*)&skv[(32 + d) * 64 + e4];
            s1.x += q1 * f1.x; s1.y += q1 * f1.y; s1.z += q1 * f1.z; s1.w += q1 * f1.w;
            s2.x += q2 * f2.x; s2.y += q2 * f2.y; s2.z += q2 * f2.z; s2.w += q2 * f2.w;
        }
        float4 a;
        a.x = s1.x - lam * s2.x; a.y = s1.y - lam * s2.y;
        a.z = s1.z - lam * s2.z; a.w = s1.w - lam * s2.w;
        *(float4*)&sA[h * 64 + e4] = a;
    }
    __syncthreads();

    if (tid < 16) {
        float ss = 0.f;
        #pragma unroll
        for (int e = 0; e < 64; e++) { float v = sA[tid * 64 + e]; ss += v * v; }
        sS[tid] = rsqrtf(ss * (1.0f/64.0f) + EPSF) * ONE_MINUS_LAM_INIT;
    }
    __syncthreads();

    // attn2 = sA * sS[h] * g2[e]; then rmsnorm over 1024 with g3 + residual
    const int i0 = tid * 4;
    const int hh = i0 >> 6;
    float v0[4];
    float ss = 0.f;
    {
        float s = sS[hh];
        float4 av = *(const float4*)&sA[i0];
        float4 gg = *(const float4*)&g2[i0 & 63];
        v0[0] = av.x * s * gg.x; v0[1] = av.y * s * gg.y;
        v0[2] = av.z * s * gg.z; v0[3] = av.w * s * gg.w;
        ss = v0[0]*v0[0] + v0[1]*v0[1] + v0[2]*v0[2] + v0[3]*v0[3];
    }
    #pragma unroll
    for (int o = 16; o > 0; o >>= 1) ss += __shfl_xor_sync(0xffffffffu, ss, o);
    if ((tid & 31) == 0) sp[tid >> 5] = ss;
    __syncthreads();
    if (tid == 0) {
        float s = 0.f;
        #pragma unroll
        for (int i = 0; i < 8; i++) s += sp[i];
        sscale = rsqrtf(s * (1.0f/1024.0f) + EPSF);
    }
    __syncthreads();
    const float sc = sscale;
    float4 g3v = ((const float4*)g3)[tid];
    float y0 = v0[0] * sc * g3v.x + v0[0];
    float y1 = v0[1] * sc * g3v.y + v0[1];
    float y2 = v0[2] * sc * g3v.z + v0[2];
    float y3 = v0[3] * sc * g3v.w + v0[3];
    ((float4*)(yp + base))[tid] = make_float4(y0, y1, y2, y3);
    split_store(ysplit, (size_t)pos, i0,     y0, y1);
    split_store(ysplit, (size_t)pos, i0 + 2, y2, y3);
}

// ============================================================
extern "C" void kernel_launch(void* const* d_in, const int* in_sizes, int n_in,
                              void* d_out, int out_size)
{
    const float* x   = (const float*)d_in[0];
    const float* Wq  = (const float*)d_in[1];
    const float* bq  = (const float*)d_in[2];
    const float* Wk  = (const float*)d_in[3];
    const float* bk  = (const float*)d_in[4];
    const float* Wv  = (const float*)d_in[5];
    const float* bv  = (const float*)d_in[6];
    const float* lp  = (const float*)d_in[7];
    const float* g1  = (const float*)d_in[8];
    const float* g2  = (const float*)d_in[9];
    const float* g3  = (const float*)d_in[10];
    const float* Wf1 = (const float*)d_in[11];
    const float* bf1 = (const float*)d_in[12];
    const float* Wf2 = (const float*)d_in[13];
    const float* bf2 = (const float*)d_in[14];
    float* out = (float*)d_out;

    float *Qp, *Kp, *Vp, *yp;
    __half *A1, *A2, *Wall;
    cudaGetSymbolAddress((void**)&Qp, g_Q);
    cudaGetSymbolAddress((void**)&Kp, g_K);
    cudaGetSymbolAddress((void**)&Vp, g_V);
    cudaGetSymbolAddress((void**)&yp, g_y);
    cudaGetSymbolAddress((void**)&A1, g_A1);
    cudaGetSymbolAddress((void**)&A2, g_A2);
    cudaGetSymbolAddress((void**)&Wall, g_W);

    cudaFuncSetAttribute(gemm_qkv,   cudaFuncAttributeMaxDynamicSharedMemorySize, SMEM_DYN);
    cudaFuncSetAttribute(gemm_tc<1>, cudaFuncAttributeMaxDynamicSharedMemorySize, SMEM_DYN);
    cudaFuncSetAttribute(gemm_tc<2>, cudaFuncAttributeMaxDynamicSharedMemorySize, SMEM_DYN);

    cvtw_all<<<5120, 256>>>(Wq, Wk, Wv, Wf1, Wf2, Wall);
    rmsnorm_k<<<M_TOT, 256>>>(x, g1, A1);

    gemm_qkv<<<dim3(24, 64), 256, SMEM_DYN>>>(A1, Wall, bq, bk, bv, Qp, Kp, Vp);

    attn_fused<<<M_TOT, 256>>>(Qp, Kp, Vp, lp, g2, g3, yp, A1);

    gemm_tc<1><<<dim3(8, 64), 256, SMEM_DYN>>>(A1, Wall + 3*WMAT, bf1, nullptr, nullptr, A2);
    gemm_tc<2><<<dim3(8, 64), 256, SMEM_DYN>>>(A2, Wall + 4*WMAT, bf2, yp, out, nullptr);
}